// round 9
// baseline (speedup 1.0000x reference)
#include <cuda_runtime.h>
#include <cuda_bf16.h>
#include <cuda_fp16.h>
#include <cuda_fp8.h>
#include <cstdint>

#define DIM 64
#define NCI_MAX 150000
#define FMA_MAX 100000
#define GATHER_BLOCKS 2048
#define GATHER_TPB 256
#define CONV_BLOCKS 512
#define ZERO_BLOCKS 64
#define HIST_BLOCKS 2048

// ---------------- scratch (device globals: allocation-free rule) ----------------
__device__ __align__(128) unsigned char g_Hn8[NCI_MAX * DIM];   // e4m3, 9.6 MB
__device__ __align__(128) unsigned char g_Hm8[NCI_MAX * DIM];   // e4m3, 9.6 MB
__device__ __align__(128) unsigned char g_Fb8[FMA_MAX * DIM];   // e4m3, 6.4 MB
__device__ float g_Nn[NCI_MAX];       // row norms |Hn_r|^2 (f32-exact)
__device__ float g_Nm[NCI_MAX];
__device__ float g_Nf[FMA_MAX];
__device__ int   g_cntN[NCI_MAX];
__device__ int   g_cntM[NCI_MAX];
__device__ int   g_cntF[FMA_MAX];
__device__ float g_part[GATHER_BLOCKS];
__device__ unsigned g_ticket;

// ---------------- HMMA: m16n8k16 bf16 -> f32 ----------------
__device__ __forceinline__ void mma16816(float* d, const uint32_t* a, const uint32_t* b) {
    asm volatile(
        "mma.sync.aligned.m16n8k16.row.col.f32.bf16.bf16.f32 "
        "{%0,%1,%2,%3}, {%4,%5,%6,%7}, {%8,%9}, {%0,%1,%2,%3};"
        : "+f"(d[0]), "+f"(d[1]), "+f"(d[2]), "+f"(d[3])
        : "r"(a[0]), "r"(a[1]), "r"(a[2]), "r"(a[3]), "r"(b[0]), "r"(b[1]));
}

#define SROW 72     // bf16 row stride for A/B tiles (conflict-free fragment loads)
#define SF8ROW 144  // byte stride for fp8 output staging (16B aligned rows)

// fp8x2 -> half2 (low byte -> .x)
__device__ __forceinline__ __half2 c8(unsigned s) {
    __half2_raw r = __nv_cvt_fp8x2_to_halfraw2((__nv_fp8x2_storage_t)(s & 0xffffu),
                                               __NV_E4M3);
    return *reinterpret_cast<__half2*>(&r);
}
__device__ __forceinline__ unsigned short f2_to_e4m3x2(float x, float y) {
    return (unsigned short)__nv_cvt_float2_to_fp8x2(make_float2(x, y),
                                                    __NV_SATFINITE, __NV_E4M3);
}

// ---------------- kernel 1: HMMA precompute + norms + F convert + counter zero ----------------
__global__ __launch_bounds__(256) void prep_mma(
    const float* __restrict__ nci,
    const float* __restrict__ Mn,
    const float* __restrict__ Mm,
    const float* __restrict__ fmae,
    int nrows, int hBlocks, int f_rows)
{
    const int tid = threadIdx.x;
    const int lane = tid & 31;

    if (blockIdx.x >= hBlocks + CONV_BLOCKS) {
        // ---- zero the histogram counters ----
        int zt = (blockIdx.x - hBlocks - CONV_BLOCKS) * 256 + tid;
        const int zs = ZERO_BLOCKS * 256;
        for (int i = zt; i < NCI_MAX; i += zs) { g_cntN[i] = 0; g_cntM[i] = 0; }
        for (int i = zt; i < FMA_MAX; i += zs) g_cntF[i] = 0;
        return;
    }

    if (blockIdx.x >= hBlocks) {
        // ---- F -> e4m3 + row norms. 8 lanes per row. ----
        const int cb = blockIdx.x - hBlocks;
        const int gw = cb * 8 + (tid >> 5);
        const int grp = lane >> 3;
        const int sub = lane & 7;
        const int rowStride = CONV_BLOCKS * 8 * 4;
        for (int row = gw * 4 + grp; row < f_rows; row += rowStride) {
            const float4* src =
                reinterpret_cast<const float4*>(fmae + (size_t)row * 64 + sub * 8);
            float4 v0 = src[0];
            float4 v1 = src[1];
            float n = v0.x * v0.x;
            n = fmaf(v0.y, v0.y, n); n = fmaf(v0.z, v0.z, n); n = fmaf(v0.w, v0.w, n);
            n = fmaf(v1.x, v1.x, n); n = fmaf(v1.y, v1.y, n);
            n = fmaf(v1.z, v1.z, n); n = fmaf(v1.w, v1.w, n);
            unsigned p0 = f2_to_e4m3x2(v0.x, v0.y);
            unsigned p1 = f2_to_e4m3x2(v0.z, v0.w);
            unsigned p2 = f2_to_e4m3x2(v1.x, v1.y);
            unsigned p3 = f2_to_e4m3x2(v1.z, v1.w);
            uint2 o;
            o.x = p0 | (p1 << 16);
            o.y = p2 | (p3 << 16);
            *reinterpret_cast<uint2*>(g_Fb8 + (size_t)row * 64 + sub * 8) = o;
#pragma unroll
            for (int off = 1; off < 8; off <<= 1)
                n += __shfl_xor_sync(0xffffffffu, n, off);
            if (sub == 0) g_Nf[row] = n;
        }
        return;
    }

    // ---- matmul tile: D[128x128] = E[128x64] @ [Mn;Mm]^T ----
    __shared__ __align__(16) unsigned char smemRaw[2 * 128 * SROW * 2];   // 36.9 KB
    __nv_bfloat16 (*sA)[SROW] = reinterpret_cast<__nv_bfloat16(*)[SROW]>(smemRaw);
    __nv_bfloat16 (*sB)[SROW] =
        reinterpret_cast<__nv_bfloat16(*)[SROW]>(smemRaw + 128 * SROW * 2);
    unsigned char* sF8 = smemRaw;   // reused after sync: 128 x SF8ROW = 18.4 KB

    const int w    = tid >> 5;
    const int gr   = lane >> 2;
    const int c    = lane & 3;
    const int rowBase = blockIdx.x * 128;

#pragma unroll
    for (int it = 0; it < 8; it++) {
        int idx = it * 256 + tid;
        int r = idx >> 4;
        int cq = idx & 15;
        int grow = rowBase + r;
        float4 v = (grow < nrows)
            ? reinterpret_cast<const float4*>(nci)[(size_t)grow * 16 + cq]
            : make_float4(0.f, 0.f, 0.f, 0.f);
        __nv_bfloat162 p0 = __floats2bfloat162_rn(v.x, v.y);
        __nv_bfloat162 p1 = __floats2bfloat162_rn(v.z, v.w);
        uint2 pk = make_uint2(*reinterpret_cast<uint32_t*>(&p0),
                              *reinterpret_cast<uint32_t*>(&p1));
        *reinterpret_cast<uint2*>(&sA[r][cq * 4]) = pk;
    }
#pragma unroll
    for (int it = 0; it < 8; it++) {
        int idx = it * 256 + tid;
        int r = idx >> 4;
        int cq = idx & 15;
        const float4* src = reinterpret_cast<const float4*>(r < 64 ? Mn : Mm);
        float4 v = src[(size_t)(r & 63) * 16 + cq];
        __nv_bfloat162 p0 = __floats2bfloat162_rn(v.x, v.y);
        __nv_bfloat162 p1 = __floats2bfloat162_rn(v.z, v.w);
        uint2 pk = make_uint2(*reinterpret_cast<uint32_t*>(&p0),
                              *reinterpret_cast<uint32_t*>(&p1));
        *reinterpret_cast<uint2*>(&sB[r][cq * 4]) = pk;
    }
    __syncthreads();

    float acc[16][4];
#pragma unroll
    for (int t = 0; t < 16; t++)
#pragma unroll
        for (int q = 0; q < 4; q++) acc[t][q] = 0.f;

#pragma unroll
    for (int kk = 0; kk < 4; kk++) {
        uint32_t a[4];
        const int ar0 = w * 16 + gr;
        const int ak  = kk * 16 + 2 * c;
        a[0] = *reinterpret_cast<const uint32_t*>(&sA[ar0][ak]);
        a[1] = *reinterpret_cast<const uint32_t*>(&sA[ar0 + 8][ak]);
        a[2] = *reinterpret_cast<const uint32_t*>(&sA[ar0][ak + 8]);
        a[3] = *reinterpret_cast<const uint32_t*>(&sA[ar0 + 8][ak + 8]);
#pragma unroll
        for (int t = 0; t < 16; t++) {
            uint32_t b[2];
            const int bn = t * 8 + gr;
            b[0] = *reinterpret_cast<const uint32_t*>(&sB[bn][ak]);
            b[1] = *reinterpret_cast<const uint32_t*>(&sB[bn][ak + 8]);
            mma16816(acc[t], a, b);
        }
    }

    // ---- row norms (f32-exact). Fragment rows r0 = w*16+gr, r1 = r0+8. ----
    float nN0 = 0.f, nN1 = 0.f, nM0 = 0.f, nM1 = 0.f;
#pragma unroll
    for (int t = 0; t < 8; t++) {
        nN0 = fmaf(acc[t][0], acc[t][0], nN0); nN0 = fmaf(acc[t][1], acc[t][1], nN0);
        nN1 = fmaf(acc[t][2], acc[t][2], nN1); nN1 = fmaf(acc[t][3], acc[t][3], nN1);
    }
#pragma unroll
    for (int t = 8; t < 16; t++) {
        nM0 = fmaf(acc[t][0], acc[t][0], nM0); nM0 = fmaf(acc[t][1], acc[t][1], nM0);
        nM1 = fmaf(acc[t][2], acc[t][2], nM1); nM1 = fmaf(acc[t][3], acc[t][3], nM1);
    }
#pragma unroll
    for (int off = 1; off < 4; off <<= 1) {
        nN0 += __shfl_xor_sync(0xffffffffu, nN0, off);
        nN1 += __shfl_xor_sync(0xffffffffu, nN1, off);
        nM0 += __shfl_xor_sync(0xffffffffu, nM0, off);
        nM1 += __shfl_xor_sync(0xffffffffu, nM1, off);
    }
    const int gr0 = rowBase + w * 16 + gr;
    const int gr1 = gr0 + 8;
    if (c == 0) {
        if (gr0 < nrows) { g_Nn[gr0] = nN0; g_Nm[gr0] = nM0; }
        if (gr1 < nrows) { g_Nn[gr1] = nN1; g_Nm[gr1] = nM1; }
    }

    // ---- fp8 epilogue: stage in smem, then coalesced 16B stores ----
    __syncthreads();    // all warps done reading sA/sB
    {
        const int r0 = w * 16 + gr;
#pragma unroll
        for (int t = 0; t < 16; t++) {
            int col = t * 8 + 2 * c;
            unsigned short v0 = f2_to_e4m3x2(acc[t][0], acc[t][1]);
            unsigned short v1 = f2_to_e4m3x2(acc[t][2], acc[t][3]);
            *reinterpret_cast<unsigned short*>(&sF8[r0 * SF8ROW + col]) = v0;
            *reinterpret_cast<unsigned short*>(&sF8[(r0 + 8) * SF8ROW + col]) = v1;
        }
    }
    __syncthreads();
#pragma unroll
    for (int it = 0; it < 4; it++) {
        int idx = it * 256 + tid;          // 1024 uint4 chunks (16 KB)
        int half = idx >> 9;               // 0 -> Hn, 1 -> Hm
        int rr = (idx >> 2) & 127;
        int ch = idx & 3;                  // 16B chunk within the 64B half-row
        int grow = rowBase + rr;
        if (grow < nrows) {
            uint4 v = *reinterpret_cast<const uint4*>(
                &sF8[rr * SF8ROW + half * 64 + ch * 16]);
            unsigned char* tab = half ? g_Hm8 : g_Hn8;
            *reinterpret_cast<uint4*>(tab + (size_t)grow * 64 + ch * 16) = v;
        }
    }
}

// ---------------- kernel 2: index histogram (exact integer adds) ----------------
__global__ __launch_bounds__(256) void hist_kernel(
    const int* __restrict__ pos_n,
    const int* __restrict__ pos_m,
    const int* __restrict__ pos_f,
    int B)
{
    int i0 = blockIdx.x * blockDim.x + threadIdx.x;
    int st = gridDim.x * blockDim.x;
    for (int i = i0; i < B; i += st) {
        atomicAdd(&g_cntN[pos_n[i]], 1);
        atomicAdd(&g_cntM[pos_m[i]], 1);
        atomicAdd(&g_cntF[pos_f[i]], 1);
    }
}

// ---------------- kernel 3: fp8 cross-term gather + norm-dot + final reduce ----------------
// loss = sum cnt*norms - 2 * sum_i (hn+hm).f   (fp8 only touches the small cross term)
__global__ __launch_bounds__(GATHER_TPB) void gather_cross(
    const int* __restrict__ pos_n,
    const int* __restrict__ pos_m,
    const int* __restrict__ pos_f,
    int B, int nrows, int f_rows, float* __restrict__ out)
{
    const int lane = threadIdx.x & 31;
    const int wloc = threadIdx.x >> 5;
    const int warp = blockIdx.x * (GATHER_TPB >> 5) + wloc;
    const int nwarp = GATHER_BLOCKS * (GATHER_TPB >> 5);
    const int grp = lane >> 3;          // sample-group 0..3 within warp-step
    const int sub = lane & 7;           // 8B chunk within 64B row

    const char* bHn = reinterpret_cast<const char*>(g_Hn8) + sub * 8;
    const char* bHm = reinterpret_cast<const char*>(g_Hm8) + sub * 8;
    const char* bFb = reinterpret_cast<const char*>(g_Fb8) + sub * 8;

    float cross = 0.f;

    for (int base = warp * 32; base < B; base += nwarp * 32) {
        const int i = base + lane;
        int vn = 0, vm = 0, vf = 0;
        if (i < B) { vn = pos_n[i]; vm = pos_m[i]; vf = pos_f[i]; }
        const int cnt = (B - base < 32) ? (B - base) : 32;

        __half2 hacc0 = __float2half2_rn(0.f);
        __half2 hacc1 = __float2half2_rn(0.f);
#pragma unroll
        for (int t = 0; t < 8; t++) {
            const int s = t * 4 + grp;
            int an = __shfl_sync(0xffffffffu, vn, s);
            int am = __shfl_sync(0xffffffffu, vm, s);
            int af = __shfl_sync(0xffffffffu, vf, s);
            if (s < cnt) {
                uint2 un = *reinterpret_cast<const uint2*>(bHn + an * 64);
                uint2 um = *reinterpret_cast<const uint2*>(bHm + am * 64);
                uint2 uf = *reinterpret_cast<const uint2*>(bFb + af * 64);
                __half2 f0 = c8(uf.x), f1 = c8(uf.x >> 16);
                __half2 f2 = c8(uf.y), f3 = c8(uf.y >> 16);
                __half2 s0 = __hadd2(c8(un.x), c8(um.x));
                __half2 s1 = __hadd2(c8(un.x >> 16), c8(um.x >> 16));
                __half2 s2 = __hadd2(c8(un.y), c8(um.y));
                __half2 s3 = __hadd2(c8(un.y >> 16), c8(um.y >> 16));
                hacc0 = __hfma2(s0, f0, hacc0);
                hacc1 = __hfma2(s1, f1, hacc1);
                hacc0 = __hfma2(s2, f2, hacc0);
                hacc1 = __hfma2(s3, f3, hacc1);
            }
        }
        float2 fl0 = __half22float2(hacc0);
        float2 fl1 = __half22float2(hacc1);
        cross += (fl0.x + fl0.y) + (fl1.x + fl1.y);
    }

    // ---- norm-dot: sum cnt * row-norm (coalesced, ~3.2 MB total across chip) ----
    float np = 0.f;
    const int gt = blockIdx.x * GATHER_TPB + threadIdx.x;
    const int gs = GATHER_BLOCKS * GATHER_TPB;
    for (int r = gt; r < nrows; r += gs)
        np += g_Nn[r] * (float)g_cntN[r] + g_Nm[r] * (float)g_cntM[r];
    for (int r = gt; r < f_rows; r += gs)
        np += 2.f * g_Nf[r] * (float)g_cntF[r];

    float acc = np - 2.f * cross;

#pragma unroll
    for (int off = 16; off > 0; off >>= 1)
        acc += __shfl_xor_sync(0xffffffffu, acc, off);

    __shared__ float ws[GATHER_TPB / 32];
    __shared__ bool isLast;
    if (lane == 0) ws[wloc] = acc;
    __syncthreads();
    if (threadIdx.x == 0) {
        float v = 0.f;
#pragma unroll
        for (int k = 0; k < GATHER_TPB / 32; k++) v += ws[k];
        g_part[blockIdx.x] = v;
        __threadfence();
        unsigned prev = atomicInc(&g_ticket, GATHER_BLOCKS - 1);
        isLast = (prev == GATHER_BLOCKS - 1);
    }
    __syncthreads();

    if (isLast) {
        float a = 0.0f;
        for (int i = threadIdx.x; i < GATHER_BLOCKS; i += GATHER_TPB)
            a += g_part[i];
#pragma unroll
        for (int off = 16; off > 0; off >>= 1)
            a += __shfl_xor_sync(0xffffffffu, a, off);
        if (lane == 0) ws[wloc] = a;
        __syncthreads();
        if (threadIdx.x == 0) {
            float v = 0.f;
#pragma unroll
            for (int k = 0; k < GATHER_TPB / 32; k++) v += ws[k];
            out[0] = v;
        }
    }
}

// ---------------- launch ----------------
extern "C" void kernel_launch(void* const* d_in, const int* in_sizes, int n_in,
                              void* d_out, int out_size)
{
    const int*   pos_n = (const int*)d_in[0];
    const int*   pos_m = (const int*)d_in[1];
    const int*   pos_f = (const int*)d_in[2];
    const float* nci   = (const float*)d_in[3];
    const float* fmae  = (const float*)d_in[4];
    const float* Mn    = (const float*)d_in[5];
    const float* Mm    = (const float*)d_in[6];

    int B = in_sizes[0];
    int nci_rows = in_sizes[3] / DIM;
    if (nci_rows > NCI_MAX) nci_rows = NCI_MAX;
    int f_rows = in_sizes[4] / DIM;
    if (f_rows > FMA_MAX) f_rows = FMA_MAX;

    int hBlocks = (nci_rows + 127) / 128;
    prep_mma<<<hBlocks + CONV_BLOCKS + ZERO_BLOCKS, 256>>>(
        nci, Mn, Mm, fmae, nci_rows, hBlocks, f_rows);
    hist_kernel<<<HIST_BLOCKS, 256>>>(pos_n, pos_m, pos_f, B);
    gather_cross<<<GATHER_BLOCKS, GATHER_TPB>>>(pos_n, pos_m, pos_f,
                                                B, nci_rows, f_rows, (float*)d_out);
}

// round 10
// speedup vs baseline: 1.2171x; 1.2171x over previous
#include <cuda_runtime.h>
#include <cuda_bf16.h>
#include <cuda_fp16.h>
#include <cuda_fp8.h>
#include <cstdint>

#define DIM 64
#define NCI_MAX 150000
#define FMA_MAX 100000
#define GATHER_BLOCKS 2048
#define GATHER_TPB 256
#define CONV_BLOCKS 512

// ---------------- scratch (device globals: allocation-free rule) ----------------
__device__ __align__(128) unsigned char g_Hn8[NCI_MAX * DIM];   // e4m3, 9.6 MB
__device__ __align__(128) unsigned char g_Hm8[NCI_MAX * DIM];   // e4m3, 9.6 MB
__device__ __align__(128) unsigned char g_Fb8[FMA_MAX * DIM];   // e4m3, 6.4 MB
__device__ float g_Nn[NCI_MAX];       // row norms |Hn_r|^2 (f32-exact)
__device__ float g_Nm[NCI_MAX];
__device__ float g_Nf[FMA_MAX];
__device__ float g_part[GATHER_BLOCKS];
__device__ unsigned g_ticket;

// ---------------- HMMA: m16n8k16 bf16 -> f32 ----------------
__device__ __forceinline__ void mma16816(float* d, const uint32_t* a, const uint32_t* b) {
    asm volatile(
        "mma.sync.aligned.m16n8k16.row.col.f32.bf16.bf16.f32 "
        "{%0,%1,%2,%3}, {%4,%5,%6,%7}, {%8,%9}, {%0,%1,%2,%3};"
        : "+f"(d[0]), "+f"(d[1]), "+f"(d[2]), "+f"(d[3])
        : "r"(a[0]), "r"(a[1]), "r"(a[2]), "r"(a[3]), "r"(b[0]), "r"(b[1]));
}

#define SROW 72     // bf16 row stride for A/B tiles (conflict-free fragment loads)
#define SF8ROW 144  // byte stride for fp8 output staging (16B aligned rows)

// fp8x2 -> half2 (low byte -> .x)
__device__ __forceinline__ __half2 c8(unsigned s) {
    __half2_raw r = __nv_cvt_fp8x2_to_halfraw2((__nv_fp8x2_storage_t)(s & 0xffffu),
                                               __NV_E4M3);
    return *reinterpret_cast<__half2*>(&r);
}
__device__ __forceinline__ unsigned short f2_to_e4m3x2(float x, float y) {
    return (unsigned short)__nv_cvt_float2_to_fp8x2(make_float2(x, y),
                                                    __NV_SATFINITE, __NV_E4M3);
}

// ---------------- kernel 1: HMMA precompute + norms + F convert ----------------
__global__ __launch_bounds__(256) void prep_mma(
    const float* __restrict__ nci,
    const float* __restrict__ Mn,
    const float* __restrict__ Mm,
    const float* __restrict__ fmae,
    int nrows, int hBlocks, int f_rows)
{
    const int tid = threadIdx.x;
    const int lane = tid & 31;

    if (blockIdx.x >= hBlocks) {
        // ---- F -> e4m3 + row norms. 8 lanes per row. ----
        const int cb = blockIdx.x - hBlocks;
        const int gw = cb * 8 + (tid >> 5);
        const int grp = lane >> 3;
        const int sub = lane & 7;
        const int rowStride = CONV_BLOCKS * 8 * 4;
        for (int row = gw * 4 + grp; row < f_rows; row += rowStride) {
            const float4* src =
                reinterpret_cast<const float4*>(fmae + (size_t)row * 64 + sub * 8);
            float4 v0 = src[0];
            float4 v1 = src[1];
            float n = v0.x * v0.x;
            n = fmaf(v0.y, v0.y, n); n = fmaf(v0.z, v0.z, n); n = fmaf(v0.w, v0.w, n);
            n = fmaf(v1.x, v1.x, n); n = fmaf(v1.y, v1.y, n);
            n = fmaf(v1.z, v1.z, n); n = fmaf(v1.w, v1.w, n);
            unsigned p0 = f2_to_e4m3x2(v0.x, v0.y);
            unsigned p1 = f2_to_e4m3x2(v0.z, v0.w);
            unsigned p2 = f2_to_e4m3x2(v1.x, v1.y);
            unsigned p3 = f2_to_e4m3x2(v1.z, v1.w);
            uint2 o;
            o.x = p0 | (p1 << 16);
            o.y = p2 | (p3 << 16);
            *reinterpret_cast<uint2*>(g_Fb8 + (size_t)row * 64 + sub * 8) = o;
#pragma unroll
            for (int off = 1; off < 8; off <<= 1)
                n += __shfl_xor_sync(0xffffffffu, n, off);
            if (sub == 0) g_Nf[row] = n;
        }
        return;
    }

    // ---- matmul tile: D[128x128] = E[128x64] @ [Mn;Mm]^T ----
    __shared__ __align__(16) unsigned char smemRaw[2 * 128 * SROW * 2];   // 36.9 KB
    __nv_bfloat16 (*sA)[SROW] = reinterpret_cast<__nv_bfloat16(*)[SROW]>(smemRaw);
    __nv_bfloat16 (*sB)[SROW] =
        reinterpret_cast<__nv_bfloat16(*)[SROW]>(smemRaw + 128 * SROW * 2);
    unsigned char* sF8 = smemRaw;   // reused after sync: 128 x SF8ROW = 18.4 KB

    const int w    = tid >> 5;
    const int gr   = lane >> 2;
    const int c    = lane & 3;
    const int rowBase = blockIdx.x * 128;

#pragma unroll
    for (int it = 0; it < 8; it++) {
        int idx = it * 256 + tid;
        int r = idx >> 4;
        int cq = idx & 15;
        int grow = rowBase + r;
        float4 v = (grow < nrows)
            ? reinterpret_cast<const float4*>(nci)[(size_t)grow * 16 + cq]
            : make_float4(0.f, 0.f, 0.f, 0.f);
        __nv_bfloat162 p0 = __floats2bfloat162_rn(v.x, v.y);
        __nv_bfloat162 p1 = __floats2bfloat162_rn(v.z, v.w);
        uint2 pk = make_uint2(*reinterpret_cast<uint32_t*>(&p0),
                              *reinterpret_cast<uint32_t*>(&p1));
        *reinterpret_cast<uint2*>(&sA[r][cq * 4]) = pk;
    }
#pragma unroll
    for (int it = 0; it < 8; it++) {
        int idx = it * 256 + tid;
        int r = idx >> 4;
        int cq = idx & 15;
        const float4* src = reinterpret_cast<const float4*>(r < 64 ? Mn : Mm);
        float4 v = src[(size_t)(r & 63) * 16 + cq];
        __nv_bfloat162 p0 = __floats2bfloat162_rn(v.x, v.y);
        __nv_bfloat162 p1 = __floats2bfloat162_rn(v.z, v.w);
        uint2 pk = make_uint2(*reinterpret_cast<uint32_t*>(&p0),
                              *reinterpret_cast<uint32_t*>(&p1));
        *reinterpret_cast<uint2*>(&sB[r][cq * 4]) = pk;
    }
    __syncthreads();

    float acc[16][4];
#pragma unroll
    for (int t = 0; t < 16; t++)
#pragma unroll
        for (int q = 0; q < 4; q++) acc[t][q] = 0.f;

#pragma unroll
    for (int kk = 0; kk < 4; kk++) {
        uint32_t a[4];
        const int ar0 = w * 16 + gr;
        const int ak  = kk * 16 + 2 * c;
        a[0] = *reinterpret_cast<const uint32_t*>(&sA[ar0][ak]);
        a[1] = *reinterpret_cast<const uint32_t*>(&sA[ar0 + 8][ak]);
        a[2] = *reinterpret_cast<const uint32_t*>(&sA[ar0][ak + 8]);
        a[3] = *reinterpret_cast<const uint32_t*>(&sA[ar0 + 8][ak + 8]);
#pragma unroll
        for (int t = 0; t < 16; t++) {
            uint32_t b[2];
            const int bn = t * 8 + gr;
            b[0] = *reinterpret_cast<const uint32_t*>(&sB[bn][ak]);
            b[1] = *reinterpret_cast<const uint32_t*>(&sB[bn][ak + 8]);
            mma16816(acc[t], a, b);
        }
    }

    // ---- row norms (f32-exact). Fragment rows r0 = w*16+gr, r1 = r0+8. ----
    float nN0 = 0.f, nN1 = 0.f, nM0 = 0.f, nM1 = 0.f;
#pragma unroll
    for (int t = 0; t < 8; t++) {
        nN0 = fmaf(acc[t][0], acc[t][0], nN0); nN0 = fmaf(acc[t][1], acc[t][1], nN0);
        nN1 = fmaf(acc[t][2], acc[t][2], nN1); nN1 = fmaf(acc[t][3], acc[t][3], nN1);
    }
#pragma unroll
    for (int t = 8; t < 16; t++) {
        nM0 = fmaf(acc[t][0], acc[t][0], nM0); nM0 = fmaf(acc[t][1], acc[t][1], nM0);
        nM1 = fmaf(acc[t][2], acc[t][2], nM1); nM1 = fmaf(acc[t][3], acc[t][3], nM1);
    }
#pragma unroll
    for (int off = 1; off < 4; off <<= 1) {
        nN0 += __shfl_xor_sync(0xffffffffu, nN0, off);
        nN1 += __shfl_xor_sync(0xffffffffu, nN1, off);
        nM0 += __shfl_xor_sync(0xffffffffu, nM0, off);
        nM1 += __shfl_xor_sync(0xffffffffu, nM1, off);
    }
    const int gr0 = rowBase + w * 16 + gr;
    const int gr1 = gr0 + 8;
    if (c == 0) {
        if (gr0 < nrows) { g_Nn[gr0] = nN0; g_Nm[gr0] = nM0; }
        if (gr1 < nrows) { g_Nn[gr1] = nN1; g_Nm[gr1] = nM1; }
    }

    // ---- fp8 epilogue: stage in smem, then coalesced 16B stores ----
    __syncthreads();    // all warps done reading sA/sB
    {
        const int r0 = w * 16 + gr;
#pragma unroll
        for (int t = 0; t < 16; t++) {
            int col = t * 8 + 2 * c;
            unsigned short v0 = f2_to_e4m3x2(acc[t][0], acc[t][1]);
            unsigned short v1 = f2_to_e4m3x2(acc[t][2], acc[t][3]);
            *reinterpret_cast<unsigned short*>(&sF8[r0 * SF8ROW + col]) = v0;
            *reinterpret_cast<unsigned short*>(&sF8[(r0 + 8) * SF8ROW + col]) = v1;
        }
    }
    __syncthreads();
#pragma unroll
    for (int it = 0; it < 4; it++) {
        int idx = it * 256 + tid;          // 1024 uint4 chunks (16 KB)
        int half = idx >> 9;               // 0 -> Hn, 1 -> Hm
        int rr = (idx >> 2) & 127;
        int ch = idx & 3;                  // 16B chunk within the 64B half-row
        int grow = rowBase + rr;
        if (grow < nrows) {
            uint4 v = *reinterpret_cast<const uint4*>(
                &sF8[rr * SF8ROW + half * 64 + ch * 16]);
            unsigned char* tab = half ? g_Hm8 : g_Hn8;
            *reinterpret_cast<uint4*>(tab + (size_t)grow * 64 + ch * 16) = v;
        }
    }
}

// ---------------- kernel 2: fp8 cross gather + per-sample norm gather + reduce ----------------
// loss = sum_i [ Nn[vn] + Nm[vm] + 2*Nf[vf] ] - 2 * sum_i (hn+hm).f
// Norms are f32-exact and gathered by index (no histogram pass, no atomics).
__global__ __launch_bounds__(GATHER_TPB) void gather_cross(
    const int* __restrict__ pos_n,
    const int* __restrict__ pos_m,
    const int* __restrict__ pos_f,
    int B, float* __restrict__ out)
{
    const int lane = threadIdx.x & 31;
    const int wloc = threadIdx.x >> 5;
    const int warp = blockIdx.x * (GATHER_TPB >> 5) + wloc;
    const int nwarp = GATHER_BLOCKS * (GATHER_TPB >> 5);
    const int grp = lane >> 3;          // sample-group 0..3 within warp-step
    const int sub = lane & 7;           // 8B chunk within 64B row

    const char* bHn = reinterpret_cast<const char*>(g_Hn8) + sub * 8;
    const char* bHm = reinterpret_cast<const char*>(g_Hm8) + sub * 8;
    const char* bFb = reinterpret_cast<const char*>(g_Fb8) + sub * 8;

    float cross = 0.f;
    float normAcc = 0.f;

    for (int base = warp * 32; base < B; base += nwarp * 32) {
        const int i = base + lane;
        int vn = 0, vm = 0, vf = 0;
        bool live = (i < B);
        if (live) { vn = pos_n[i]; vm = pos_m[i]; vf = pos_f[i]; }

        // per-lane exact norm contribution for its own sample
        if (live)
            normAcc += g_Nn[vn] + g_Nm[vm] + 2.0f * g_Nf[vf];

        const int cnt = (B - base < 32) ? (B - base) : 32;
        __half2 hacc0 = __float2half2_rn(0.f);
        __half2 hacc1 = __float2half2_rn(0.f);
#pragma unroll
        for (int t = 0; t < 8; t++) {
            const int s = t * 4 + grp;
            int an = __shfl_sync(0xffffffffu, vn, s);
            int am = __shfl_sync(0xffffffffu, vm, s);
            int af = __shfl_sync(0xffffffffu, vf, s);
            if (s < cnt) {
                uint2 un = *reinterpret_cast<const uint2*>(bHn + an * 64);
                uint2 um = *reinterpret_cast<const uint2*>(bHm + am * 64);
                uint2 uf = *reinterpret_cast<const uint2*>(bFb + af * 64);
                __half2 f0 = c8(uf.x), f1 = c8(uf.x >> 16);
                __half2 f2 = c8(uf.y), f3 = c8(uf.y >> 16);
                __half2 s0 = __hadd2(c8(un.x), c8(um.x));
                __half2 s1 = __hadd2(c8(un.x >> 16), c8(um.x >> 16));
                __half2 s2 = __hadd2(c8(un.y), c8(um.y));
                __half2 s3 = __hadd2(c8(un.y >> 16), c8(um.y >> 16));
                hacc0 = __hfma2(s0, f0, hacc0);
                hacc1 = __hfma2(s1, f1, hacc1);
                hacc0 = __hfma2(s2, f2, hacc0);
                hacc1 = __hfma2(s3, f3, hacc1);
            }
        }
        float2 fl0 = __half22float2(hacc0);
        float2 fl1 = __half22float2(hacc1);
        cross += (fl0.x + fl0.y) + (fl1.x + fl1.y);
    }

    float acc = normAcc - 2.f * cross;

#pragma unroll
    for (int off = 16; off > 0; off >>= 1)
        acc += __shfl_xor_sync(0xffffffffu, acc, off);

    __shared__ float ws[GATHER_TPB / 32];
    __shared__ bool isLast;
    if (lane == 0) ws[wloc] = acc;
    __syncthreads();
    if (threadIdx.x == 0) {
        float v = 0.f;
#pragma unroll
        for (int k = 0; k < GATHER_TPB / 32; k++) v += ws[k];
        g_part[blockIdx.x] = v;
        __threadfence();
        unsigned prev = atomicInc(&g_ticket, GATHER_BLOCKS - 1);
        isLast = (prev == GATHER_BLOCKS - 1);
    }
    __syncthreads();

    if (isLast) {
        float a = 0.0f;
        for (int i = threadIdx.x; i < GATHER_BLOCKS; i += GATHER_TPB)
            a += g_part[i];
#pragma unroll
        for (int off = 16; off > 0; off >>= 1)
            a += __shfl_xor_sync(0xffffffffu, a, off);
        if (lane == 0) ws[wloc] = a;
        __syncthreads();
        if (threadIdx.x == 0) {
            float v = 0.f;
#pragma unroll
            for (int k = 0; k < GATHER_TPB / 32; k++) v += ws[k];
            out[0] = v;
        }
    }
}

// ---------------- launch ----------------
extern "C" void kernel_launch(void* const* d_in, const int* in_sizes, int n_in,
                              void* d_out, int out_size)
{
    const int*   pos_n = (const int*)d_in[0];
    const int*   pos_m = (const int*)d_in[1];
    const int*   pos_f = (const int*)d_in[2];
    const float* nci   = (const float*)d_in[3];
    const float* fmae  = (const float*)d_in[4];
    const float* Mn    = (const float*)d_in[5];
    const float* Mm    = (const float*)d_in[6];

    int B = in_sizes[0];
    int nci_rows = in_sizes[3] / DIM;
    if (nci_rows > NCI_MAX) nci_rows = NCI_MAX;
    int f_rows = in_sizes[4] / DIM;
    if (f_rows > FMA_MAX) f_rows = FMA_MAX;

    int hBlocks = (nci_rows + 127) / 128;
    prep_mma<<<hBlocks + CONV_BLOCKS, 256>>>(
        nci, Mn, Mm, fmae, nci_rows, hBlocks, f_rows);
    gather_cross<<<GATHER_BLOCKS, GATHER_TPB>>>(pos_n, pos_m, pos_f,
                                                B, (float*)d_out);
}

// round 11
// speedup vs baseline: 1.2291x; 1.0098x over previous
#include <cuda_runtime.h>
#include <cuda_bf16.h>
#include <cuda_fp16.h>
#include <cuda_fp8.h>
#include <cstdint>

#define DIM 64
#define NCI_MAX 150000
#define FMA_MAX 100000
#define GATHER_BLOCKS 2048
#define GATHER_TPB 256
#define CONV_BLOCKS 512

// ---------------- scratch (device globals: allocation-free rule) ----------------
__device__ __align__(128) unsigned char g_Hn8[NCI_MAX * DIM];   // e4m3, 9.6 MB
__device__ __align__(128) unsigned char g_Hm8[NCI_MAX * DIM];   // e4m3, 9.6 MB
__device__ __align__(128) unsigned char g_Fb8[FMA_MAX * DIM];   // e4m3, 6.4 MB
__device__ float g_Nn[NCI_MAX];       // row norms |Hn_r|^2 (f32-exact)
__device__ float g_Nm[NCI_MAX];
__device__ float g_Nf[FMA_MAX];
__device__ float g_part[GATHER_BLOCKS];
__device__ unsigned g_ticket;

// ---------------- HMMA: m16n8k16 bf16 -> f32 ----------------
__device__ __forceinline__ void mma16816(float* d, const uint32_t* a, const uint32_t* b) {
    asm volatile(
        "mma.sync.aligned.m16n8k16.row.col.f32.bf16.bf16.f32 "
        "{%0,%1,%2,%3}, {%4,%5,%6,%7}, {%8,%9}, {%0,%1,%2,%3};"
        : "+f"(d[0]), "+f"(d[1]), "+f"(d[2]), "+f"(d[3])
        : "r"(a[0]), "r"(a[1]), "r"(a[2]), "r"(a[3]), "r"(b[0]), "r"(b[1]));
}

#define SROW 72      // bf16 row stride for A/B tiles (conflict-free fragment loads)
#define STG_STRIDE 80 // byte stride for fp8 half-tile staging (16B-aligned rows)

// fp8x2 -> half2 (low byte -> .x)
__device__ __forceinline__ __half2 c8(unsigned s) {
    __half2_raw r = __nv_cvt_fp8x2_to_halfraw2((__nv_fp8x2_storage_t)(s & 0xffffu),
                                               __NV_E4M3);
    return *reinterpret_cast<__half2*>(&r);
}
__device__ __forceinline__ unsigned short f2_to_e4m3x2(float x, float y) {
    return (unsigned short)__nv_cvt_float2_to_fp8x2(make_float2(x, y),
                                                    __NV_SATFINITE, __NV_E4M3);
}

// ---------------- kernel 1: HMMA precompute (split-N) + norms + F convert ----------------
__global__ __launch_bounds__(256) void prep_mma(
    const float* __restrict__ nci,
    const float* __restrict__ Mn,
    const float* __restrict__ Mm,
    const float* __restrict__ fmae,
    int nrows, int hBlocks, int f_rows)
{
    const int tid = threadIdx.x;
    const int lane = tid & 31;

    if (blockIdx.x >= hBlocks) {
        // ---- F -> e4m3 + row norms. 8 lanes per row. ----
        const int cb = blockIdx.x - hBlocks;
        const int gw = cb * 8 + (tid >> 5);
        const int grp = lane >> 3;
        const int sub = lane & 7;
        const int rowStride = CONV_BLOCKS * 8 * 4;
        for (int row = gw * 4 + grp; row < f_rows; row += rowStride) {
            const float4* src =
                reinterpret_cast<const float4*>(fmae + (size_t)row * 64 + sub * 8);
            float4 v0 = src[0];
            float4 v1 = src[1];
            float n = v0.x * v0.x;
            n = fmaf(v0.y, v0.y, n); n = fmaf(v0.z, v0.z, n); n = fmaf(v0.w, v0.w, n);
            n = fmaf(v1.x, v1.x, n); n = fmaf(v1.y, v1.y, n);
            n = fmaf(v1.z, v1.z, n); n = fmaf(v1.w, v1.w, n);
            unsigned p0 = f2_to_e4m3x2(v0.x, v0.y);
            unsigned p1 = f2_to_e4m3x2(v0.z, v0.w);
            unsigned p2 = f2_to_e4m3x2(v1.x, v1.y);
            unsigned p3 = f2_to_e4m3x2(v1.z, v1.w);
            uint2 o;
            o.x = p0 | (p1 << 16);
            o.y = p2 | (p3 << 16);
            *reinterpret_cast<uint2*>(g_Fb8 + (size_t)row * 64 + sub * 8) = o;
#pragma unroll
            for (int off = 1; off < 8; off <<= 1)
                n += __shfl_xor_sync(0xffffffffu, n, off);
            if (sub == 0) g_Nf[row] = n;
        }
        return;
    }

    // ---- matmul tile: D[128x128] = E[128x64] @ [Mn;Mm]^T, processed as two
    //      64-col halves (half 0 -> Hn + Nn, half 1 -> Hm + Nm). ----
    __shared__ __align__(16) __nv_bfloat16 sA[128][SROW];        // 18.4 KB
    __shared__ __align__(16) __nv_bfloat16 sB[128][SROW];        // 18.4 KB
    __shared__ __align__(16) unsigned char sStg[128 * STG_STRIDE]; // 10.0 KB

    const int w    = tid >> 5;
    const int gr   = lane >> 2;
    const int c    = lane & 3;
    const int rowBase = blockIdx.x * 128;

#pragma unroll
    for (int it = 0; it < 8; it++) {
        int idx = it * 256 + tid;
        int r = idx >> 4;
        int cq = idx & 15;
        int grow = rowBase + r;
        float4 v = (grow < nrows)
            ? reinterpret_cast<const float4*>(nci)[(size_t)grow * 16 + cq]
            : make_float4(0.f, 0.f, 0.f, 0.f);
        __nv_bfloat162 p0 = __floats2bfloat162_rn(v.x, v.y);
        __nv_bfloat162 p1 = __floats2bfloat162_rn(v.z, v.w);
        uint2 pk = make_uint2(*reinterpret_cast<uint32_t*>(&p0),
                              *reinterpret_cast<uint32_t*>(&p1));
        *reinterpret_cast<uint2*>(&sA[r][cq * 4]) = pk;
    }
#pragma unroll
    for (int it = 0; it < 8; it++) {
        int idx = it * 256 + tid;
        int r = idx >> 4;
        int cq = idx & 15;
        const float4* src = reinterpret_cast<const float4*>(r < 64 ? Mn : Mm);
        float4 v = src[(size_t)(r & 63) * 16 + cq];
        __nv_bfloat162 p0 = __floats2bfloat162_rn(v.x, v.y);
        __nv_bfloat162 p1 = __floats2bfloat162_rn(v.z, v.w);
        uint2 pk = make_uint2(*reinterpret_cast<uint32_t*>(&p0),
                              *reinterpret_cast<uint32_t*>(&p1));
        *reinterpret_cast<uint2*>(&sB[r][cq * 4]) = pk;
    }
    __syncthreads();

#pragma unroll
    for (int half = 0; half < 2; half++) {
        float acc[8][4];
#pragma unroll
        for (int t = 0; t < 8; t++)
#pragma unroll
            for (int q = 0; q < 4; q++) acc[t][q] = 0.f;

#pragma unroll
        for (int kk = 0; kk < 4; kk++) {
            uint32_t a[4];
            const int ar0 = w * 16 + gr;
            const int ak  = kk * 16 + 2 * c;
            a[0] = *reinterpret_cast<const uint32_t*>(&sA[ar0][ak]);
            a[1] = *reinterpret_cast<const uint32_t*>(&sA[ar0 + 8][ak]);
            a[2] = *reinterpret_cast<const uint32_t*>(&sA[ar0][ak + 8]);
            a[3] = *reinterpret_cast<const uint32_t*>(&sA[ar0 + 8][ak + 8]);
#pragma unroll
            for (int t = 0; t < 8; t++) {
                uint32_t b[2];
                const int bn = (half * 8 + t) * 8 + gr;
                b[0] = *reinterpret_cast<const uint32_t*>(&sB[bn][ak]);
                b[1] = *reinterpret_cast<const uint32_t*>(&sB[bn][ak + 8]);
                mma16816(acc[t], a, b);
            }
        }

        // ---- row norms (f32-exact) for this half ----
        float n0 = 0.f, n1 = 0.f;
#pragma unroll
        for (int t = 0; t < 8; t++) {
            n0 = fmaf(acc[t][0], acc[t][0], n0); n0 = fmaf(acc[t][1], acc[t][1], n0);
            n1 = fmaf(acc[t][2], acc[t][2], n1); n1 = fmaf(acc[t][3], acc[t][3], n1);
        }
#pragma unroll
        for (int off = 1; off < 4; off <<= 1) {
            n0 += __shfl_xor_sync(0xffffffffu, n0, off);
            n1 += __shfl_xor_sync(0xffffffffu, n1, off);
        }
        const int gr0 = rowBase + w * 16 + gr;
        const int gr1 = gr0 + 8;
        float* ntab = half ? g_Nm : g_Nn;
        if (c == 0) {
            if (gr0 < nrows) ntab[gr0] = n0;
            if (gr1 < nrows) ntab[gr1] = n1;
        }

        // ---- fp8 epilogue for this half: stage, then coalesced 16B stores ----
        __syncthreads();   // previous users of sStg done (and sA/sB reads finished this pass)
        {
            const int r0 = w * 16 + gr;
#pragma unroll
            for (int t = 0; t < 8; t++) {
                int col = t * 8 + 2 * c;           // 0..63
                unsigned short v0 = f2_to_e4m3x2(acc[t][0], acc[t][1]);
                unsigned short v1 = f2_to_e4m3x2(acc[t][2], acc[t][3]);
                *reinterpret_cast<unsigned short*>(&sStg[r0 * STG_STRIDE + col]) = v0;
                *reinterpret_cast<unsigned short*>(&sStg[(r0 + 8) * STG_STRIDE + col]) = v1;
            }
        }
        __syncthreads();
        unsigned char* tab = half ? g_Hm8 : g_Hn8;
#pragma unroll
        for (int it = 0; it < 2; it++) {
            int idx = it * 256 + tid;              // 512 uint4 chunks (8 KB)
            int rr = idx >> 2;                     // 0..127
            int ch = idx & 3;                      // 16B chunk within 64B row
            int grow = rowBase + rr;
            if (grow < nrows) {
                uint4 v = *reinterpret_cast<const uint4*>(
                    &sStg[rr * STG_STRIDE + ch * 16]);
                *reinterpret_cast<uint4*>(tab + (size_t)grow * 64 + ch * 16) = v;
            }
        }
    }
}

// ---------------- kernel 2: fp8 cross gather + per-sample norm gather + reduce ----------------
// loss = sum_i [ Nn[vn] + Nm[vm] + 2*Nf[vf] ] - 2 * sum_i (hn+hm).f
__global__ __launch_bounds__(GATHER_TPB) void gather_cross(
    const int* __restrict__ pos_n,
    const int* __restrict__ pos_m,
    const int* __restrict__ pos_f,
    int B, float* __restrict__ out)
{
    const int lane = threadIdx.x & 31;
    const int wloc = threadIdx.x >> 5;
    const int warp = blockIdx.x * (GATHER_TPB >> 5) + wloc;
    const int nwarp = GATHER_BLOCKS * (GATHER_TPB >> 5);
    const int grp = lane >> 3;          // sample-group 0..3 within warp-step
    const int sub = lane & 7;           // 8B chunk within 64B row

    const char* bHn = reinterpret_cast<const char*>(g_Hn8) + sub * 8;
    const char* bHm = reinterpret_cast<const char*>(g_Hm8) + sub * 8;
    const char* bFb = reinterpret_cast<const char*>(g_Fb8) + sub * 8;

    float cross = 0.f;
    float normAcc = 0.f;

    for (int base = warp * 32; base < B; base += nwarp * 32) {
        const int i = base + lane;
        int vn = 0, vm = 0, vf = 0;
        bool live = (i < B);
        if (live) { vn = pos_n[i]; vm = pos_m[i]; vf = pos_f[i]; }

        if (live)
            normAcc += g_Nn[vn] + g_Nm[vm] + 2.0f * g_Nf[vf];

        const int cnt = (B - base < 32) ? (B - base) : 32;
        __half2 hacc0 = __float2half2_rn(0.f);
        __half2 hacc1 = __float2half2_rn(0.f);
#pragma unroll
        for (int t = 0; t < 8; t++) {
            const int s = t * 4 + grp;
            int an = __shfl_sync(0xffffffffu, vn, s);
            int am = __shfl_sync(0xffffffffu, vm, s);
            int af = __shfl_sync(0xffffffffu, vf, s);
            if (s < cnt) {
                uint2 un = *reinterpret_cast<const uint2*>(bHn + an * 64);
                uint2 um = *reinterpret_cast<const uint2*>(bHm + am * 64);
                uint2 uf = *reinterpret_cast<const uint2*>(bFb + af * 64);
                __half2 f0 = c8(uf.x), f1 = c8(uf.x >> 16);
                __half2 f2 = c8(uf.y), f3 = c8(uf.y >> 16);
                __half2 s0 = __hadd2(c8(un.x), c8(um.x));
                __half2 s1 = __hadd2(c8(un.x >> 16), c8(um.x >> 16));
                __half2 s2 = __hadd2(c8(un.y), c8(um.y));
                __half2 s3 = __hadd2(c8(un.y >> 16), c8(um.y >> 16));
                hacc0 = __hfma2(s0, f0, hacc0);
                hacc1 = __hfma2(s1, f1, hacc1);
                hacc0 = __hfma2(s2, f2, hacc0);
                hacc1 = __hfma2(s3, f3, hacc1);
            }
        }
        float2 fl0 = __half22float2(hacc0);
        float2 fl1 = __half22float2(hacc1);
        cross += (fl0.x + fl0.y) + (fl1.x + fl1.y);
    }

    float acc = normAcc - 2.f * cross;

#pragma unroll
    for (int off = 16; off > 0; off >>= 1)
        acc += __shfl_xor_sync(0xffffffffu, acc, off);

    __shared__ float ws[GATHER_TPB / 32];
    __shared__ bool isLast;
    if (lane == 0) ws[wloc] = acc;
    __syncthreads();
    if (threadIdx.x == 0) {
        float v = 0.f;
#pragma unroll
        for (int k = 0; k < GATHER_TPB / 32; k++) v += ws[k];
        g_part[blockIdx.x] = v;
        __threadfence();
        unsigned prev = atomicInc(&g_ticket, GATHER_BLOCKS - 1);
        isLast = (prev == GATHER_BLOCKS - 1);
    }
    __syncthreads();

    if (isLast) {
        float a = 0.0f;
        for (int i = threadIdx.x; i < GATHER_BLOCKS; i += GATHER_TPB)
            a += g_part[i];
#pragma unroll
        for (int off = 16; off > 0; off >>= 1)
            a += __shfl_xor_sync(0xffffffffu, a, off);
        if (lane == 0) ws[wloc] = a;
        __syncthreads();
        if (threadIdx.x == 0) {
            float v = 0.f;
#pragma unroll
            for (int k = 0; k < GATHER_TPB / 32; k++) v += ws[k];
            out[0] = v;
        }
    }
}

// ---------------- launch ----------------
extern "C" void kernel_launch(void* const* d_in, const int* in_sizes, int n_in,
                              void* d_out, int out_size)
{
    const int*   pos_n = (const int*)d_in[0];
    const int*   pos_m = (const int*)d_in[1];
    const int*   pos_f = (const int*)d_in[2];
    const float* nci   = (const float*)d_in[3];
    const float* fmae  = (const float*)d_in[4];
    const float* Mn    = (const float*)d_in[5];
    const float* Mm    = (const float*)d_in[6];

    int B = in_sizes[0];
    int nci_rows = in_sizes[3] / DIM;
    if (nci_rows > NCI_MAX) nci_rows = NCI_MAX;
    int f_rows = in_sizes[4] / DIM;
    if (f_rows > FMA_MAX) f_rows = FMA_MAX;

    int hBlocks = (nci_rows + 127) / 128;
    prep_mma<<<hBlocks + CONV_BLOCKS, 256>>>(
        nci, Mn, Mm, fmae, nci_rows, hBlocks, f_rows);
    gather_cross<<<GATHER_BLOCKS, GATHER_TPB>>>(pos_n, pos_m, pos_f,
                                                B, (float*)d_out);
}